// round 15
// baseline (speedup 1.0000x reference)
#include <cuda_runtime.h>
#include <cuda_bf16.h>
#include <math.h>
#include <stdint.h>

#define BDIM 2
#define TDIM 2048
#define CDIM 1024
#define HDIM 64
#define NH   16
#define NKV  8
#define MROWS (BDIM*TDIM)   // 4096
#define QKV_COLS 2048       // 1024 q | 512 k | 512 v

// Arch-specific feature gate: tcgen05 only exists in the sm_103a pass.
#if defined(__CUDA_ARCH__) && defined(__CUDA_ARCH_FEAT_SM103_ALL)
#define HAS_TCGEN05 1
#else
#define HAS_TCGEN05 0
#endif

// ---------------- scratch (device globals: no allocation allowed) -------------
__device__ float g_qkv[(size_t)MROWS * QKV_COLS];     // fused q|k|v raw, 32MB
__device__ float g_sq[(size_t)BDIM * NH * TDIM];
__device__ float g_sk[(size_t)BDIM * NKV * TDIM];

__device__ __nv_bfloat16 g_xhi[(size_t)MROWS * CDIM];
__device__ __nv_bfloat16 g_xlo[(size_t)MROWS * CDIM];
__device__ __nv_bfloat16 g_wqkvh[(size_t)QKV_COLS * CDIM];   // Wq|Wk|Wv hi
__device__ __nv_bfloat16 g_wqkvl[(size_t)QKV_COLS * CDIM];   // Wq|Wk|Wv lo
__device__ __nv_bfloat16 g_wph[(size_t)CDIM * CDIM];
__device__ __nv_bfloat16 g_wpl[(size_t)CDIM * CDIM];
__device__ __nv_bfloat16 g_yhi[(size_t)MROWS * CDIM];
__device__ __nv_bfloat16 g_ylo[(size_t)MROWS * CDIM];

// =================== tcgen05 helpers (guarded) ===============================
#if HAS_TCGEN05
__device__ __forceinline__ uint32_t smem_u32(const void* p) {
    uint32_t a;
    asm("{ .reg .u64 t; cvta.to.shared.u64 t, %1; cvt.u32.u64 %0, t; }" : "=r"(a) : "l"(p));
    return a;
}
__device__ __forceinline__ uint32_t elect_one() {
    uint32_t pred;
    asm volatile("{\n\t.reg .pred p;\n\telect.sync _|p, 0xFFFFFFFF;\n\tselp.b32 %0, 1, 0, p;\n\t}" : "=r"(pred));
    return pred;
}
#define TC_ALLOC(smem_addr, n)  asm volatile("tcgen05.alloc.cta_group::1.sync.aligned.shared::cta.b32 [%0], %1;" :: "r"(smem_addr), "r"(n) : "memory")
#define TC_DEALLOC(tmem, n)     asm volatile("tcgen05.dealloc.cta_group::1.sync.aligned.b32 %0, %1;" :: "r"(tmem), "r"(n))
#define TC_COMMIT(mbar)         asm volatile("tcgen05.commit.cta_group::1.mbarrier::arrive::one.shared::cluster.b64 [%0];" :: "r"(mbar) : "memory")
#define TC_FENCE_AFTER()        asm volatile("tcgen05.fence::after_thread_sync;" ::: "memory")
#define TC_FENCE_BEFORE()       asm volatile("tcgen05.fence::before_thread_sync;" ::: "memory")
#define TC_WAIT_LD()            asm volatile("tcgen05.wait::ld.sync.aligned;" ::: "memory")
#define MBAR_INIT(mbar, cnt)    asm volatile("mbarrier.init.shared.b64 [%0], %1;" :: "r"(mbar), "r"(cnt) : "memory")

__device__ __forceinline__ void mbar_wait(uint32_t mbar, uint32_t parity) {
    asm volatile(
        "{\n\t.reg .pred P;\n\t"
        "W%=:\n\t"
        "mbarrier.try_wait.parity.acquire.cta.shared::cta.b64 P, [%0], %1, 0x989680;\n\t"
        "@P bra.uni D%=;\n\t"
        "bra.uni W%=;\n\t"
        "D%=:\n\t}"
        :: "r"(mbar), "r"(parity) : "memory");
}
__device__ __forceinline__ void tc_mma_f16_ss(uint32_t d_tmem, uint64_t a_desc, uint64_t b_desc,
                                              uint32_t idesc, uint32_t en) {
    asm volatile(
        "{\n\t.reg .pred p;\n\tsetp.ne.u32 p, %4, 0;\n\t"
        "tcgen05.mma.cta_group::1.kind::f16 [%0], %1, %2, %3, {%5, %5, %5, %5}, p;\n\t}"
        :: "r"(d_tmem), "l"(a_desc), "l"(b_desc), "r"(idesc), "r"(en), "r"(0u) : "memory");
}
__device__ __forceinline__ void ldtm_x32(uint32_t* r, uint32_t tmem) {
    asm volatile(
        "tcgen05.ld.sync.aligned.32x32b.x32.b32 "
        "{%0, %1, %2, %3, %4, %5, %6, %7, %8, %9, %10, %11, %12, %13, %14, %15, "
        " %16, %17, %18, %19, %20, %21, %22, %23, %24, %25, %26, %27, %28, %29, %30, %31}, [%32];"
        : "=r"(r[0]), "=r"(r[1]), "=r"(r[2]), "=r"(r[3]), "=r"(r[4]), "=r"(r[5]), "=r"(r[6]), "=r"(r[7]),
          "=r"(r[8]), "=r"(r[9]), "=r"(r[10]), "=r"(r[11]), "=r"(r[12]), "=r"(r[13]), "=r"(r[14]), "=r"(r[15]),
          "=r"(r[16]), "=r"(r[17]), "=r"(r[18]), "=r"(r[19]), "=r"(r[20]), "=r"(r[21]), "=r"(r[22]), "=r"(r[23]),
          "=r"(r[24]), "=r"(r[25]), "=r"(r[26]), "=r"(r[27]), "=r"(r[28]), "=r"(r[29]), "=r"(r[30]), "=r"(r[31])
        : "r"(tmem));
}
#define DESC_BASE ((uint64_t(2) << 61) | (uint64_t(1) << 46) | (uint64_t(64) << 32) | (uint64_t(1) << 16))
__device__ __forceinline__ uint64_t mk_desc(uint32_t addr) {
    return DESC_BASE | ((uint64_t)(addr >> 4) & 0x3FFF);
}
#endif // HAS_TCGEN05

// ================= bf16-split GEMM: C[M,N] = sum_k A[m,k]*B[n,k] =============
// 3-pass K extension, tile 128x128, KT=64, 3-STAGE pipelined SMEM ring:
// load(it+2) only needs MMA(it-1) done -> two iterations of latency slack.
#define SOFF_TM  0
#define SOFF_MB  8                          // three mbarriers at 8,16,24
#define SOFF_AB(s) (1024 + (s) * 32768)     // stage s: A 16KB then B 16KB
#define SMEM_GEMM (1024 + 3 * 32768)        // 99328

// idesc: F32 acc, BF16 x BF16, N=128, M=128
#define GEMM_IDESC ((1u<<4) | (1u<<7) | (1u<<10) | ((128u/8)<<17) | ((128u/16)<<24))

__global__ __launch_bounds__(256)
#if HAS_TCGEN05
__cluster_dims__(1, 1, 1)
#endif
void gemm3_bf16(
    const __nv_bfloat16* __restrict__ Ahi, const __nv_bfloat16* __restrict__ Alo,
    const __nv_bfloat16* __restrict__ Bhi, const __nv_bfloat16* __restrict__ Blo,
    float* __restrict__ C, int M, int NC, int K)
{
#if HAS_TCGEN05
    extern __shared__ char smem[];
    const uint32_t sbase = smem_u32(smem);
    const int tid  = threadIdx.x;
    const int wid  = tid >> 5;
    const int lane = tid & 31;
    const int m0 = blockIdx.y * 128;
    const int n0 = blockIdx.x * 128;

    if (wid == 0) { TC_ALLOC(sbase + SOFF_TM, 128); }
    if (tid == 0) {
        MBAR_INIT(sbase + SOFF_MB,      1);
        MBAR_INIT(sbase + SOFF_MB + 8,  1);
        MBAR_INIT(sbase + SOFF_MB + 16, 1);
    }
    __syncthreads();
    uint32_t tmem;
    asm volatile("ld.shared.b32 %0, [%1];" : "=r"(tmem) : "r"(sbase + SOFF_TM));

    const int ipp = K / 64;
    const int NIT = 3 * ipp;                // 48 for K=1024

    // fill stage `st` with tile for iteration `it` (A 128x64 + B 128x64 bf16)
    auto load_iter = [&](int it, int st) {
        const int pass = it / ipp;
        const int kk   = (it - pass * ipp) * 64;
        const __nv_bfloat16* Asrc = (pass < 2) ? Ahi : Alo;
        const __nv_bfloat16* Bsrc = (pass == 1) ? Blo : Bhi;
        char* const base = smem + SOFF_AB(st);
        #pragma unroll
        for (int i = 0; i < 8; i++) {
            const int j = i * 256 + tid;          // 0..2047 16B-chunks
            const bool isA = j < 1024;
            const int jj  = isA ? j : j - 1024;
            const int row = jj >> 3;
            const int c16 = jj & 7;
            const __nv_bfloat16* src = isA
                ? Asrc + ((size_t)(m0 + row) * K + kk + c16 * 8)
                : Bsrc + ((size_t)(n0 + row) * K + kk + c16 * 8);
            uint4 v = *(const uint4*)src;
            uint32_t off = row * 128 + c16 * 16;
            uint32_t sw  = off ^ ((off >> 3) & 0x70);
            *(uint4*)(base + (isA ? 0 : 16384) + sw) = v;
        }
        TC_FENCE_BEFORE();
    };

    load_iter(0, 0);
    load_iter(1, 1);
    __syncthreads();

    uint32_t ph[3] = {0u, 0u, 0u};
    for (int it = 0; it < NIT; ++it) {
        const int st = it % 3;
        if (wid == 0) {
            TC_FENCE_AFTER();
            if (elect_one()) {
                uint64_t ad = mk_desc(sbase + SOFF_AB(st));
                uint64_t bd = mk_desc(sbase + SOFF_AB(st) + 16384);
                #pragma unroll
                for (int ks = 0; ks < 4; ks++)
                    tc_mma_f16_ss(tmem, ad + ks * 2, bd + ks * 2, GEMM_IDESC,
                                  (it == 0 && ks == 0) ? 0u : 1u);
                TC_COMMIT(sbase + SOFF_MB + 8 * st);
            }
        }
        if (it + 2 < NIT) {
            const int s2 = (it + 2) % 3;          // last used by MMA(it-1)
            if (it >= 1) { mbar_wait(sbase + SOFF_MB + 8 * s2, ph[s2]); ph[s2] ^= 1; }
            load_iter(it + 2, s2);
        }
        __syncthreads();
    }

    const int lb = (NIT - 1) % 3;
    mbar_wait(sbase + SOFF_MB + 8 * lb, ph[lb]);
    TC_FENCE_AFTER();

    if (wid < 4) {
        uint32_t r[64];
        #pragma unroll
        for (int half = 0; half < 2; half++) {
            ldtm_x32(r,      tmem + half * 64);
            ldtm_x32(r + 32, tmem + half * 64 + 32);
            TC_WAIT_LD();
            float* crow = C + (size_t)(m0 + wid * 32 + lane) * NC + n0 + half * 64;
            #pragma unroll
            for (int c = 0; c < 64; c += 4) {
                float4 o = make_float4(__uint_as_float(r[c]),   __uint_as_float(r[c+1]),
                                       __uint_as_float(r[c+2]), __uint_as_float(r[c+3]));
                *(float4*)(crow + c) = o;
            }
        }
        TC_FENCE_BEFORE();
    }
    __syncthreads();
    if (wid == 0) { TC_DEALLOC(tmem, 128); }
#else
    // -------- FFMA fallback (non-103a pass; functionally exact) --------------
    extern __shared__ char smem_raw[];
    float* As = (float*)smem_raw;
    float* Bs = As + 8 * 128;

    const int tid  = threadIdx.x;
    const int m0   = blockIdx.y * 128;
    const int n0   = blockIdx.x * 128;
    const int lrow = tid >> 1;
    const int lk4  = (tid & 1) * 4;
    const int ty   = tid >> 4;
    const int tx   = tid & 15;

    const __nv_bfloat16* Ah = Ahi + (size_t)(m0 + lrow) * K;
    const __nv_bfloat16* Al = Alo + (size_t)(m0 + lrow) * K;
    const __nv_bfloat16* Bh = Bhi + (size_t)(n0 + lrow) * K;
    const __nv_bfloat16* Bl = Blo + (size_t)(n0 + lrow) * K;

    float acc[8][8];
    #pragma unroll
    for (int i = 0; i < 8; i++)
        #pragma unroll
        for (int j = 0; j < 8; j++) acc[i][j] = 0.f;

    for (int kt = 0; kt < K; kt += 8) {
        #pragma unroll
        for (int j = 0; j < 4; j++) {
            As[(lk4+j)*128 + lrow] = __bfloat162float(Ah[kt+lk4+j]) + __bfloat162float(Al[kt+lk4+j]);
            Bs[(lk4+j)*128 + lrow] = __bfloat162float(Bh[kt+lk4+j]) + __bfloat162float(Bl[kt+lk4+j]);
        }
        __syncthreads();
        #pragma unroll
        for (int kk = 0; kk < 8; kk++) {
            float a[8], b[8];
            #pragma unroll
            for (int i = 0; i < 8; i++) a[i] = As[kk*128 + ty*8 + i];
            #pragma unroll
            for (int j = 0; j < 8; j++) b[j] = Bs[kk*128 + tx*8 + j];
            #pragma unroll
            for (int i = 0; i < 8; i++)
                #pragma unroll
                for (int j = 0; j < 8; j++)
                    acc[i][j] = fmaf(a[i], b[j], acc[i][j]);
        }
        __syncthreads();
    }
    #pragma unroll
    for (int i = 0; i < 8; i++) {
        float* crow = C + (size_t)(m0 + ty*8 + i) * NC + n0 + tx*8;
        ((float4*)crow)[0] = make_float4(acc[i][0], acc[i][1], acc[i][2], acc[i][3]);
        ((float4*)crow)[1] = make_float4(acc[i][4], acc[i][5], acc[i][6], acc[i][7]);
    }
#endif
}

// ---------------- fp32 -> bf16 hi/lo split (elementwise) ---------------------
__global__ __launch_bounds__(256) void split_bf16(
    const float* __restrict__ src, __nv_bfloat16* __restrict__ hi,
    __nv_bfloat16* __restrict__ lo, int n4)
{
    int i = blockIdx.x * 256 + threadIdx.x;
    if (i >= n4) return;
    float4 v = ((const float4*)src)[i];
    float f[4] = {v.x, v.y, v.z, v.w};
    __nv_bfloat16 h[4], l[4];
    #pragma unroll
    for (int j = 0; j < 4; j++) {
        h[j] = __float2bfloat16(f[j]);
        l[j] = __float2bfloat16(f[j] - __bfloat162float(h[j]));
    }
    ((__nv_bfloat162*)hi)[2*i]   = __halves2bfloat162(h[0], h[1]);
    ((__nv_bfloat162*)hi)[2*i+1] = __halves2bfloat162(h[2], h[3]);
    ((__nv_bfloat162*)lo)[2*i]   = __halves2bfloat162(l[0], l[1]);
    ((__nv_bfloat162*)lo)[2*i+1] = __halves2bfloat162(l[2], l[3]);
}

// ------------- RoPE + RMSnorm + braid dot: one warp per (b,t,h) row ----------
__global__ __launch_bounds__(256) void rope_braid(
    const float* __restrict__ qkv, float* __restrict__ sout,
    const float* __restrict__ cosb, const float* __restrict__ sinb,
    const float* __restrict__ wb, int nheads, int col0)
{
    const int rid  = blockIdx.x * 8 + (threadIdx.x >> 5);
    const int lane = threadIdx.x & 31;
    const int total = BDIM * TDIM * nheads;
    if (rid >= total) return;

    const int h  = rid % nheads;
    const int bt = rid / nheads;
    const int t  = bt % TDIM;
    const int b  = bt / TDIM;

    const float* base = qkv + (size_t)bt * QKV_COLS + col0 + h * HDIM;
    const float x1 = base[lane];
    const float x2 = base[lane + 32];
    const float c  = cosb[t*32 + lane];
    const float s  = sinb[t*32 + lane];

    const float r1 = x1*c + x2*s;
    const float r2 = x2*c - x1*s;

    float ss = r1*r1 + r2*r2;
    #pragma unroll
    for (int o = 16; o; o >>= 1) ss += __shfl_xor_sync(0xffffffffu, ss, o);
    const float scale = rsqrtf(ss * (1.0f/64.0f) + 1e-6f);

    float sv = (r1*wb[lane] + r2*wb[lane+32]) * scale;
    #pragma unroll
    for (int o = 16; o; o >>= 1) sv += __shfl_xor_sync(0xffffffffu, sv, o);

    if (lane == 0)
        sout[((size_t)b*nheads + h) * TDIM + t] = sv;
}

// ========== tensor-core attention: y = (1/sqrt T) sig(sq+sk)|causal @ v ======
#define ATT_TMPTR 0
#define ATT_MBAR  8
#define ATT_PH    1024                 // P hi  [128t x 128s] bf16 = 32KB
#define ATT_PL    (1024 + 32768)       // P lo
#define ATT_VH    (1024 + 65536)       // V^T hi [64d x 128s] bf16 = 16KB
#define ATT_VL    (1024 + 65536 + 16384)
#define ATT_ESK   (1024 + 65536 + 32768)   // 128 floats, AFTER tiles
#define SMEM_ATTN (1024 + 65536 + 32768 + 512)   // 99840

// idesc: F32 acc, BF16 x BF16, N=64, M=128
#define ATT_IDESC ((1u<<4) | (1u<<7) | (1u<<10) | ((64u/8)<<17) | ((128u/16)<<24))

#define SW128(x) ((x) ^ (((x) >> 3) & 0x70))
__device__ __forceinline__ uint32_t a_off(int t, int s) {   // A: 128 rows -> 16 atom-rows
    return (uint32_t)(((t >> 3) + (s >> 6) * 16) * 1024 + (t & 7) * 128 + (s & 63) * 2);
}
__device__ __forceinline__ uint32_t b_off(int d, int s) {   // B: 64 rows -> 8 atom-rows
    return (uint32_t)(((d >> 3) + (s >> 6) * 8) * 1024 + (d & 7) * 128 + (s & 63) * 2);
}

__global__ __launch_bounds__(128)
#if HAS_TCGEN05
__cluster_dims__(1, 1, 1)
#endif
void braid_attn_tc()
{
    const int bh = blockIdx.y;
    const int b  = bh >> 4;
    const int h  = bh & 15;
    const int kh = h >> 1;
    const int t0 = (int)(gridDim.x - 1 - blockIdx.x) * 128;
    const int tl = threadIdx.x;
    const int t  = t0 + tl;
    const float sq = g_sq[(size_t)bh * TDIM + t];
    const float* skb  = g_sk + ((size_t)b * NKV + kh) * TDIM;
    const float* vsrc = g_qkv + (size_t)b * TDIM * QKV_COLS + 1536 + kh * HDIM;

#if HAS_TCGEN05
    extern __shared__ char smem[];
    const uint32_t sbase = smem_u32(smem);
    const int wid  = tl >> 5;

    if (wid == 0) { TC_ALLOC(sbase + ATT_TMPTR, 64); }
    if (tl == 0)  { MBAR_INIT(sbase + ATT_MBAR, 1); }
    __syncthreads();
    uint32_t tmem;
    asm volatile("ld.shared.b32 %0, [%1];" : "=r"(tmem) : "r"(sbase + ATT_TMPTR));

    const float E = __expf(-fminf(fmaxf(sq, -80.f), 80.f));
    float* eskp = (float*)(smem + ATT_ESK);

    uint32_t ph = 0;
    const int ntiles = t0 / 128 + 1;
    for (int it = 0; it < ntiles; ++it) {
        const int s0 = it * 128;
        if (it > 0) { mbar_wait(sbase + ATT_MBAR, ph); ph ^= 1; }   // SMEM free

        {
            float skv = skb[s0 + tl];
            eskp[tl] = __expf(-fminf(fmaxf(skv, -80.f), 80.f));
        }

        // V^T tile: [64 d rows x 128 s] bf16 hi/lo, blocked-atom + SW128
        #pragma unroll 4
        for (int i = 0; i < 32; i++) {
            const int idx = i * 128 + tl;
            const int d  = idx & 63;
            const int s  = (idx >> 6) * 2;
            const float v0 = vsrc[(size_t)(s0 + s)     * QKV_COLS + d];
            const float v1 = vsrc[(size_t)(s0 + s + 1) * QKV_COLS + d];
            __nv_bfloat162 h2 = __floats2bfloat162_rn(v0, v1);
            float l0 = v0 - __bfloat162float(__low2bfloat16(h2));
            float l1 = v1 - __bfloat162float(__high2bfloat16(h2));
            __nv_bfloat162 l2 = __floats2bfloat162_rn(l0, l1);
            const uint32_t off = SW128(b_off(d, s));
            *(__nv_bfloat162*)(smem + ATT_VH + off) = h2;
            *(__nv_bfloat162*)(smem + ATT_VL + off) = l2;
        }
        __syncthreads();   // esk table complete before P loop

        // P row: p = 1/(1 + E*esk[s]), causal-masked
        const int lim = (s0 == t0) ? tl : 127;
        #pragma unroll 4
        for (int j = 0; j < 64; j++) {
            const int s = 2 * j;
            const float2 e2 = ((const float2*)eskp)[j];
            float p0 = (s     <= lim) ? __fdividef(1.f, fmaf(E, e2.x, 1.f)) : 0.f;
            float p1 = (s + 1 <= lim) ? __fdividef(1.f, fmaf(E, e2.y, 1.f)) : 0.f;
            __nv_bfloat162 h2 = __floats2bfloat162_rn(p0, p1);
            float l0 = p0 - __bfloat162float(__low2bfloat16(h2));
            float l1 = p1 - __bfloat162float(__high2bfloat16(h2));
            __nv_bfloat162 l2 = __floats2bfloat162_rn(l0, l1);
            const uint32_t off = SW128(a_off(tl, s));
            *(__nv_bfloat162*)(smem + ATT_PH + off) = h2;
            *(__nv_bfloat162*)(smem + ATT_PL + off) = l2;
        }
        TC_FENCE_BEFORE();
        __syncthreads();

        if (wid == 0) {
            TC_FENCE_AFTER();
            if (elect_one()) {
                const uint64_t pa_h = mk_desc(sbase + ATT_PH);
                const uint64_t pa_l = mk_desc(sbase + ATT_PL);
                const uint64_t vb_h = mk_desc(sbase + ATT_VH);
                const uint64_t vb_l = mk_desc(sbase + ATT_VL);
                #pragma unroll
                for (int term = 0; term < 3; term++) {
                    const uint64_t ad = (term == 2) ? pa_l : pa_h;
                    const uint64_t bd = (term == 1) ? vb_l : vb_h;
                    #pragma unroll
                    for (int ks = 0; ks < 8; ks++) {
                        const uint64_t ao = (ks < 4) ? (uint64_t)(ks * 2) : (uint64_t)(1024 + (ks - 4) * 2);
                        const uint64_t bo = (ks < 4) ? (uint64_t)(ks * 2) : (uint64_t)(512  + (ks - 4) * 2);
                        tc_mma_f16_ss(tmem, ad + ao, bd + bo, ATT_IDESC,
                                      (it == 0 && term == 0 && ks == 0) ? 0u : 1u);
                    }
                }
                TC_COMMIT(sbase + ATT_MBAR);
            }
        }
    }

    mbar_wait(sbase + ATT_MBAR, ph);
    TC_FENCE_AFTER();

    uint32_t r[64];
    ldtm_x32(r,      tmem);
    ldtm_x32(r + 32, tmem + 32);
    TC_WAIT_LD();
    TC_FENCE_BEFORE();

    const float inv = 1.0f / (45.25483399593904f + 1e-6f);
    __nv_bfloat16* yh = g_yhi + (size_t)(b * TDIM + t) * CDIM + h * HDIM;
    __nv_bfloat16* yl = g_ylo + (size_t)(b * TDIM + t) * CDIM + h * HDIM;
    #pragma unroll
    for (int i = 0; i < 64; i += 2) {
        float v0 = __uint_as_float(r[i])   * inv;
        float v1 = __uint_as_float(r[i+1]) * inv;
        __nv_bfloat162 h2 = __floats2bfloat162_rn(v0, v1);
        float l0 = v0 - __bfloat162float(__low2bfloat16(h2));
        float l1 = v1 - __bfloat162float(__high2bfloat16(h2));
        *(__nv_bfloat162*)(yh + i) = h2;
        *(__nv_bfloat162*)(yl + i) = __floats2bfloat162_rn(l0, l1);
    }
    __syncthreads();
    if (wid == 0) { TC_DEALLOC(tmem, 64); }
#else
    // -------- FFMA fallback (compile-only on non-103a pass) ------------------
    float acc[64];
    #pragma unroll
    for (int i = 0; i < 64; i++) acc[i] = 0.f;
    for (int s = 0; s <= t; s++) {
        float p = __fdividef(1.0f, 1.0f + __expf(-(sq + skb[s])));
        const float* vr = vsrc + (size_t)s * QKV_COLS;
        #pragma unroll
        for (int i = 0; i < 64; i++) acc[i] = fmaf(p, vr[i], acc[i]);
    }
    const float inv = 1.0f / (45.25483399593904f + 1e-6f);
    __nv_bfloat16* yh = g_yhi + (size_t)(b * TDIM + t) * CDIM + h * HDIM;
    __nv_bfloat16* yl = g_ylo + (size_t)(b * TDIM + t) * CDIM + h * HDIM;
    #pragma unroll
    for (int i = 0; i < 64; i += 2) {
        float v0 = acc[i] * inv, v1 = acc[i+1] * inv;
        __nv_bfloat162 h2 = __floats2bfloat162_rn(v0, v1);
        float l0 = v0 - __bfloat162float(__low2bfloat16(h2));
        float l1 = v1 - __bfloat162float(__high2bfloat16(h2));
        *(__nv_bfloat162*)(yh + i) = h2;
        *(__nv_bfloat162*)(yl + i) = __floats2bfloat162_rn(l0, l1);
    }
#endif
}

// -----------------------------------------------------------------------------
extern "C" void kernel_launch(void* const* d_in, const int* in_sizes, int n_in,
                              void* d_out, int out_size)
{
    const float* x     = (const float*)d_in[0];
    const float* cosb  = (const float*)d_in[1];
    const float* sinb  = (const float*)d_in[2];
    const float* Wq    = (const float*)d_in[3];
    const float* Wk    = (const float*)d_in[4];
    const float* Wv    = (const float*)d_in[5];
    const float* Wproj = (const float*)d_in[6];
    const float* wb    = (const float*)d_in[7];
    float* out = (float*)d_out;

    float *qkv, *sq, *sk;
    cudaGetSymbolAddress((void**)&qkv, g_qkv);
    cudaGetSymbolAddress((void**)&sq,  g_sq);
    cudaGetSymbolAddress((void**)&sk,  g_sk);

    __nv_bfloat16 *xhi, *xlo, *wqkvh, *wqkvl, *wph, *wpl, *yhi, *ylo;
    cudaGetSymbolAddress((void**)&xhi,   g_xhi);    cudaGetSymbolAddress((void**)&xlo,   g_xlo);
    cudaGetSymbolAddress((void**)&wqkvh, g_wqkvh);  cudaGetSymbolAddress((void**)&wqkvl, g_wqkvl);
    cudaGetSymbolAddress((void**)&wph,   g_wph);    cudaGetSymbolAddress((void**)&wpl,   g_wpl);
    cudaGetSymbolAddress((void**)&yhi,   g_yhi);    cudaGetSymbolAddress((void**)&ylo,   g_ylo);

    cudaFuncSetAttribute(gemm3_bf16,    cudaFuncAttributeMaxDynamicSharedMemorySize, SMEM_GEMM);
    cudaFuncSetAttribute(braid_attn_tc, cudaFuncAttributeMaxDynamicSharedMemorySize, SMEM_ATTN);

    // hi/lo bf16 splits (Wq|Wk|Wv go into one fused weight buffer)
    {
        int n4;
        n4 = MROWS*CDIM/4;      split_bf16<<<(n4+255)/256, 256>>>(x,     xhi, xlo, n4);
        n4 = CDIM*CDIM/4;       split_bf16<<<(n4+255)/256, 256>>>(Wq,    wqkvh,                wqkvl,                n4);
        n4 = (NKV*HDIM)*CDIM/4; split_bf16<<<(n4+255)/256, 256>>>(Wk,    wqkvh + 1024*CDIM,    wqkvl + 1024*CDIM,    n4);
        n4 = (NKV*HDIM)*CDIM/4; split_bf16<<<(n4+255)/256, 256>>>(Wv,    wqkvh + 1536*CDIM,    wqkvl + 1536*CDIM,    n4);
        n4 = CDIM*CDIM/4;       split_bf16<<<(n4+255)/256, 256>>>(Wproj, wph, wpl, n4);
    }

    // fused QKV projection: [4096 x 2048] = x @ [Wq|Wk|Wv]^T on tcgen05
    gemm3_bf16<<<dim3(QKV_COLS/128, MROWS/128), 256, SMEM_GEMM>>>(
        xhi, xlo, wqkvh, wqkvl, qkv, MROWS, QKV_COLS, CDIM);

    // RoPE + RMSnorm + braid scalar (q cols 0..1023, k cols 1024..1535)
    rope_braid<<<(BDIM*TDIM*NH  + 7) / 8, 256>>>(qkv, sq, cosb, sinb, wb, NH,  0);
    rope_braid<<<(BDIM*TDIM*NKV + 7) / 8, 256>>>(qkv, sk, cosb, sinb, wb, NKV, 1024);

    // tensor-core sigmoid-braid causal attention -> y (bf16 hi/lo)
    braid_attn_tc<<<dim3(TDIM/128, BDIM*NH), 128, SMEM_ATTN>>>();

    // output projection
    gemm3_bf16<<<dim3(CDIM/128, MROWS/128), 256, SMEM_GEMM>>>(
        yhi, ylo, wph, wpl, out, MROWS, CDIM, CDIM);
}

// round 16
// speedup vs baseline: 1.3020x; 1.3020x over previous
#include <cuda_runtime.h>
#include <cuda.h>
#include <cuda_bf16.h>
#include <math.h>
#include <stdint.h>

#define BDIM 2
#define TDIM 2048
#define CDIM 1024
#define HDIM 64
#define NH   16
#define NKV  8
#define MROWS (BDIM*TDIM)   // 4096
#define QKV_COLS 2048       // 1024 q | 512 k | 512 v

// Arch-specific feature gate: tcgen05 only exists in the sm_103a pass.
#if defined(__CUDA_ARCH__) && defined(__CUDA_ARCH_FEAT_SM103_ALL)
#define HAS_TCGEN05 1
#else
#define HAS_TCGEN05 0
#endif

// ---------------- scratch (device globals: no allocation allowed) -------------
__device__ float g_qkv[(size_t)MROWS * QKV_COLS];     // fused q|k|v raw, 32MB
__device__ float g_sq[(size_t)BDIM * NH * TDIM];
__device__ float g_sk[(size_t)BDIM * NKV * TDIM];

__device__ __nv_bfloat16 g_xhi[(size_t)MROWS * CDIM];
__device__ __nv_bfloat16 g_xlo[(size_t)MROWS * CDIM];
__device__ __nv_bfloat16 g_wqkvh[(size_t)QKV_COLS * CDIM];   // Wq|Wk|Wv hi
__device__ __nv_bfloat16 g_wqkvl[(size_t)QKV_COLS * CDIM];   // Wq|Wk|Wv lo
__device__ __nv_bfloat16 g_wph[(size_t)CDIM * CDIM];
__device__ __nv_bfloat16 g_wpl[(size_t)CDIM * CDIM];
__device__ __nv_bfloat16 g_yhi[(size_t)MROWS * CDIM];
__device__ __nv_bfloat16 g_ylo[(size_t)MROWS * CDIM];

// =================== tcgen05 helpers (guarded) ===============================
#if HAS_TCGEN05
__device__ __forceinline__ uint32_t smem_u32(const void* p) {
    uint32_t a;
    asm("{ .reg .u64 t; cvta.to.shared.u64 t, %1; cvt.u32.u64 %0, t; }" : "=r"(a) : "l"(p));
    return a;
}
__device__ __forceinline__ uint32_t elect_one() {
    uint32_t pred;
    asm volatile("{\n\t.reg .pred p;\n\telect.sync _|p, 0xFFFFFFFF;\n\tselp.b32 %0, 1, 0, p;\n\t}" : "=r"(pred));
    return pred;
}
#define TC_ALLOC(smem_addr, n)  asm volatile("tcgen05.alloc.cta_group::1.sync.aligned.shared::cta.b32 [%0], %1;" :: "r"(smem_addr), "r"(n) : "memory")
#define TC_DEALLOC(tmem, n)     asm volatile("tcgen05.dealloc.cta_group::1.sync.aligned.b32 %0, %1;" :: "r"(tmem), "r"(n))
#define TC_COMMIT(mbar)         asm volatile("tcgen05.commit.cta_group::1.mbarrier::arrive::one.shared::cluster.b64 [%0];" :: "r"(mbar) : "memory")
#define TC_FENCE_AFTER()        asm volatile("tcgen05.fence::after_thread_sync;" ::: "memory")
#define TC_FENCE_BEFORE()       asm volatile("tcgen05.fence::before_thread_sync;" ::: "memory")
#define TC_WAIT_LD()            asm volatile("tcgen05.wait::ld.sync.aligned;" ::: "memory")
#define MBAR_INIT(mbar, cnt)    asm volatile("mbarrier.init.shared.b64 [%0], %1;" :: "r"(mbar), "r"(cnt) : "memory")
#define MBAR_EXPECT_TX(mbar, n) asm volatile("mbarrier.arrive.expect_tx.shared.b64 _, [%0], %1;" :: "r"(mbar), "r"(n) : "memory")
#define TMA_2D(smem, map, cx, cy, mbar) \
    asm volatile("cp.async.bulk.tensor.2d.shared::cta.global.tile.mbarrier::complete_tx::bytes " \
                 "[%0], [%1, {%2, %3}], [%4];" \
                 :: "r"(smem), "l"(map), "r"(cx), "r"(cy), "r"(mbar) : "memory")

__device__ __forceinline__ void mbar_wait(uint32_t mbar, uint32_t parity) {
    asm volatile(
        "{\n\t.reg .pred P;\n\t"
        "W%=:\n\t"
        "mbarrier.try_wait.parity.acquire.cta.shared::cta.b64 P, [%0], %1, 0x989680;\n\t"
        "@P bra.uni D%=;\n\t"
        "bra.uni W%=;\n\t"
        "D%=:\n\t}"
        :: "r"(mbar), "r"(parity) : "memory");
}
__device__ __forceinline__ void tc_mma_f16_ss(uint32_t d_tmem, uint64_t a_desc, uint64_t b_desc,
                                              uint32_t idesc, uint32_t en) {
    asm volatile(
        "{\n\t.reg .pred p;\n\tsetp.ne.u32 p, %4, 0;\n\t"
        "tcgen05.mma.cta_group::1.kind::f16 [%0], %1, %2, %3, {%5, %5, %5, %5}, p;\n\t}"
        :: "r"(d_tmem), "l"(a_desc), "l"(b_desc), "r"(idesc), "r"(en), "r"(0u) : "memory");
}
__device__ __forceinline__ void ldtm_x32(uint32_t* r, uint32_t tmem) {
    asm volatile(
        "tcgen05.ld.sync.aligned.32x32b.x32.b32 "
        "{%0, %1, %2, %3, %4, %5, %6, %7, %8, %9, %10, %11, %12, %13, %14, %15, "
        " %16, %17, %18, %19, %20, %21, %22, %23, %24, %25, %26, %27, %28, %29, %30, %31}, [%32];"
        : "=r"(r[0]), "=r"(r[1]), "=r"(r[2]), "=r"(r[3]), "=r"(r[4]), "=r"(r[5]), "=r"(r[6]), "=r"(r[7]),
          "=r"(r[8]), "=r"(r[9]), "=r"(r[10]), "=r"(r[11]), "=r"(r[12]), "=r"(r[13]), "=r"(r[14]), "=r"(r[15]),
          "=r"(r[16]), "=r"(r[17]), "=r"(r[18]), "=r"(r[19]), "=r"(r[20]), "=r"(r[21]), "=r"(r[22]), "=r"(r[23]),
          "=r"(r[24]), "=r"(r[25]), "=r"(r[26]), "=r"(r[27]), "=r"(r[28]), "=r"(r[29]), "=r"(r[30]), "=r"(r[31])
        : "r"(tmem));
}
#define DESC_BASE ((uint64_t(2) << 61) | (uint64_t(1) << 46) | (uint64_t(64) << 32) | (uint64_t(1) << 16))
__device__ __forceinline__ uint64_t mk_desc(uint32_t addr) {
    return DESC_BASE | ((uint64_t)(addr >> 4) & 0x3FFF);
}
#endif // HAS_TCGEN05

// ================= bf16-split GEMM via TMA: C = sum_k A[m,k]*B[n,k] ==========
// 3-pass K extension, tile 128x128, KT=64, 3-stage TMA ring, single-thread
// orchestration (full/free mbarrier pairs), MMA floor <-> LTS-bound loads.
#define SOFF_TM    0
#define SOFF_FULL(s) (8  + (s) * 8)
#define SOFF_FREE(s) (32 + (s) * 8)
#define SOFF_AB(s) (1024 + (s) * 32768)     // stage s: A 16KB then B 16KB
#define SMEM_GEMM (1024 + 3 * 32768)        // 99328

// idesc: F32 acc, BF16 x BF16, N=128, M=128
#define GEMM_IDESC ((1u<<4) | (1u<<7) | (1u<<10) | ((128u/8)<<17) | ((128u/16)<<24))

__global__ __launch_bounds__(256)
#if HAS_TCGEN05
__cluster_dims__(1, 1, 1)
#endif
void gemm3_bf16(
    const __grid_constant__ CUtensorMap tAhi, const __grid_constant__ CUtensorMap tAlo,
    const __grid_constant__ CUtensorMap tBhi, const __grid_constant__ CUtensorMap tBlo,
    const __nv_bfloat16* __restrict__ Ahi, const __nv_bfloat16* __restrict__ Alo,
    const __nv_bfloat16* __restrict__ Bhi, const __nv_bfloat16* __restrict__ Blo,
    float* __restrict__ C, int M, int NC, int K)
{
#if HAS_TCGEN05
    extern __shared__ char smem[];
    const uint32_t sbase = smem_u32(smem);
    const int tid  = threadIdx.x;
    const int wid  = tid >> 5;
    const int lane = tid & 31;
    const int m0 = blockIdx.y * 128;
    const int n0 = blockIdx.x * 128;

    if (wid == 0) { TC_ALLOC(sbase + SOFF_TM, 128); }
    if (tid == 0) {
        #pragma unroll
        for (int s = 0; s < 3; s++) {
            MBAR_INIT(sbase + SOFF_FULL(s), 1);
            MBAR_INIT(sbase + SOFF_FREE(s), 1);
        }
    }
    __syncthreads();
    uint32_t tmem;
    asm volatile("ld.shared.b32 %0, [%1];" : "=r"(tmem) : "r"(sbase + SOFF_TM));

    const int ipp = K / 64;
    const int NIT = 3 * ipp;                // 48 for K=1024

    if (wid == 0 && elect_one()) {
        // issue loads for iteration `it` into stage `st`
        auto issue_load = [&](int it, int st) {
            const int pass = it / ipp;
            const int kk   = (it - pass * ipp) * 64;
            const CUtensorMap* am = (pass < 2)  ? &tAhi : &tAlo;
            const CUtensorMap* bm = (pass == 1) ? &tBlo : &tBhi;
            const uint32_t mb = sbase + SOFF_FULL(st);
            MBAR_EXPECT_TX(mb, 32768u);
            TMA_2D(sbase + SOFF_AB(st),         am, kk, m0, mb);
            TMA_2D(sbase + SOFF_AB(st) + 16384, bm, kk, n0, mb);
        };

        issue_load(0, 0);
        issue_load(1, 1);
        issue_load(2, 2);

        uint32_t phF[3] = {0u, 0u, 0u};
        uint32_t phE[3] = {0u, 0u, 0u};
        for (int it = 0; it < NIT; ++it) {
            const int st = it % 3;
            mbar_wait(sbase + SOFF_FULL(st), phF[st]); phF[st] ^= 1;
            uint64_t ad = mk_desc(sbase + SOFF_AB(st));
            uint64_t bd = mk_desc(sbase + SOFF_AB(st) + 16384);
            #pragma unroll
            for (int ks = 0; ks < 4; ks++)
                tc_mma_f16_ss(tmem, ad + ks * 2, bd + ks * 2, GEMM_IDESC,
                              (it == 0 && ks == 0) ? 0u : 1u);
            TC_COMMIT(sbase + SOFF_FREE(st));
            if (it + 3 < NIT) {
                mbar_wait(sbase + SOFF_FREE(st), phE[st]); phE[st] ^= 1;  // MMA(it) done
                issue_load(it + 3, st);
            }
        }
        // drain: last commit (stage (NIT-1)%3) implies all prior MMAs done
        const int lb = (NIT - 1) % 3;
        mbar_wait(sbase + SOFF_FREE(lb), phE[lb]);
    }
    __syncthreads();
    TC_FENCE_AFTER();

    if (wid < 4) {
        uint32_t r[64];
        #pragma unroll
        for (int half = 0; half < 2; half++) {
            ldtm_x32(r,      tmem + half * 64);
            ldtm_x32(r + 32, tmem + half * 64 + 32);
            TC_WAIT_LD();
            float* crow = C + (size_t)(m0 + wid * 32 + lane) * NC + n0 + half * 64;
            #pragma unroll
            for (int c = 0; c < 64; c += 4) {
                float4 o = make_float4(__uint_as_float(r[c]),   __uint_as_float(r[c+1]),
                                       __uint_as_float(r[c+2]), __uint_as_float(r[c+3]));
                *(float4*)(crow + c) = o;
            }
        }
        TC_FENCE_BEFORE();
    }
    __syncthreads();
    if (wid == 0) { TC_DEALLOC(tmem, 128); }
#else
    // -------- FFMA fallback (non-103a pass; functionally exact) --------------
    extern __shared__ char smem_raw[];
    float* As = (float*)smem_raw;
    float* Bs = As + 8 * 128;

    const int tid  = threadIdx.x;
    const int m0   = blockIdx.y * 128;
    const int n0   = blockIdx.x * 128;
    const int lrow = tid >> 1;
    const int lk4  = (tid & 1) * 4;
    const int ty   = tid >> 4;
    const int tx   = tid & 15;

    const __nv_bfloat16* Ah = Ahi + (size_t)(m0 + lrow) * K;
    const __nv_bfloat16* Al = Alo + (size_t)(m0 + lrow) * K;
    const __nv_bfloat16* Bh = Bhi + (size_t)(n0 + lrow) * K;
    const __nv_bfloat16* Bl = Blo + (size_t)(n0 + lrow) * K;

    float acc[8][8];
    #pragma unroll
    for (int i = 0; i < 8; i++)
        #pragma unroll
        for (int j = 0; j < 8; j++) acc[i][j] = 0.f;

    for (int kt = 0; kt < K; kt += 8) {
        #pragma unroll
        for (int j = 0; j < 4; j++) {
            As[(lk4+j)*128 + lrow] = __bfloat162float(Ah[kt+lk4+j]) + __bfloat162float(Al[kt+lk4+j]);
            Bs[(lk4+j)*128 + lrow] = __bfloat162float(Bh[kt+lk4+j]) + __bfloat162float(Bl[kt+lk4+j]);
        }
        __syncthreads();
        #pragma unroll
        for (int kk = 0; kk < 8; kk++) {
            float a[8], b[8];
            #pragma unroll
            for (int i = 0; i < 8; i++) a[i] = As[kk*128 + ty*8 + i];
            #pragma unroll
            for (int j = 0; j < 8; j++) b[j] = Bs[kk*128 + tx*8 + j];
            #pragma unroll
            for (int i = 0; i < 8; i++)
                #pragma unroll
                for (int j = 0; j < 8; j++)
                    acc[i][j] = fmaf(a[i], b[j], acc[i][j]);
        }
        __syncthreads();
    }
    #pragma unroll
    for (int i = 0; i < 8; i++) {
        float* crow = C + (size_t)(m0 + ty*8 + i) * NC + n0 + tx*8;
        ((float4*)crow)[0] = make_float4(acc[i][0], acc[i][1], acc[i][2], acc[i][3]);
        ((float4*)crow)[1] = make_float4(acc[i][4], acc[i][5], acc[i][6], acc[i][7]);
    }
#endif
}

// ---------------- fp32 -> bf16 hi/lo split (elementwise) ---------------------
__global__ __launch_bounds__(256) void split_bf16(
    const float* __restrict__ src, __nv_bfloat16* __restrict__ hi,
    __nv_bfloat16* __restrict__ lo, int n4)
{
    int i = blockIdx.x * 256 + threadIdx.x;
    if (i >= n4) return;
    float4 v = ((const float4*)src)[i];
    float f[4] = {v.x, v.y, v.z, v.w};
    __nv_bfloat16 h[4], l[4];
    #pragma unroll
    for (int j = 0; j < 4; j++) {
        h[j] = __float2bfloat16(f[j]);
        l[j] = __float2bfloat16(f[j] - __bfloat162float(h[j]));
    }
    ((__nv_bfloat162*)hi)[2*i]   = __halves2bfloat162(h[0], h[1]);
    ((__nv_bfloat162*)hi)[2*i+1] = __halves2bfloat162(h[2], h[3]);
    ((__nv_bfloat162*)lo)[2*i]   = __halves2bfloat162(l[0], l[1]);
    ((__nv_bfloat162*)lo)[2*i+1] = __halves2bfloat162(l[2], l[3]);
}

// ------------- RoPE + RMSnorm + braid dot: one warp per (b,t,h) row ----------
__global__ __launch_bounds__(256) void rope_braid(
    const float* __restrict__ qkv, float* __restrict__ sout,
    const float* __restrict__ cosb, const float* __restrict__ sinb,
    const float* __restrict__ wb, int nheads, int col0)
{
    const int rid  = blockIdx.x * 8 + (threadIdx.x >> 5);
    const int lane = threadIdx.x & 31;
    const int total = BDIM * TDIM * nheads;
    if (rid >= total) return;

    const int h  = rid % nheads;
    const int bt = rid / nheads;
    const int t  = bt % TDIM;
    const int b  = bt / TDIM;

    const float* base = qkv + (size_t)bt * QKV_COLS + col0 + h * HDIM;
    const float x1 = base[lane];
    const float x2 = base[lane + 32];
    const float c  = cosb[t*32 + lane];
    const float s  = sinb[t*32 + lane];

    const float r1 = x1*c + x2*s;
    const float r2 = x2*c - x1*s;

    float ss = r1*r1 + r2*r2;
    #pragma unroll
    for (int o = 16; o; o >>= 1) ss += __shfl_xor_sync(0xffffffffu, ss, o);
    const float scale = rsqrtf(ss * (1.0f/64.0f) + 1e-6f);

    float sv = (r1*wb[lane] + r2*wb[lane+32]) * scale;
    #pragma unroll
    for (int o = 16; o; o >>= 1) sv += __shfl_xor_sync(0xffffffffu, sv, o);

    if (lane == 0)
        sout[((size_t)b*nheads + h) * TDIM + t] = sv;
}

// ========== tensor-core attention: y = (1/sqrt T) sig(sq+sk)|causal @ v ======
#define ATT_TMPTR 0
#define ATT_MBAR  8
#define ATT_PH    1024                 // P hi  [128t x 128s] bf16 = 32KB
#define ATT_PL    (1024 + 32768)       // P lo
#define ATT_VH    (1024 + 65536)       // V^T hi [64d x 128s] bf16 = 16KB
#define ATT_VL    (1024 + 65536 + 16384)
#define ATT_ESK   (1024 + 65536 + 32768)   // 128 floats, AFTER tiles
#define SMEM_ATTN (1024 + 65536 + 32768 + 512)   // 99840

// idesc: F32 acc, BF16 x BF16, N=64, M=128
#define ATT_IDESC ((1u<<4) | (1u<<7) | (1u<<10) | ((64u/8)<<17) | ((128u/16)<<24))

#define SW128(x) ((x) ^ (((x) >> 3) & 0x70))
__device__ __forceinline__ uint32_t a_off(int t, int s) {   // A: 128 rows -> 16 atom-rows
    return (uint32_t)(((t >> 3) + (s >> 6) * 16) * 1024 + (t & 7) * 128 + (s & 63) * 2);
}
__device__ __forceinline__ uint32_t b_off(int d, int s) {   // B: 64 rows -> 8 atom-rows
    return (uint32_t)(((d >> 3) + (s >> 6) * 8) * 1024 + (d & 7) * 128 + (s & 63) * 2);
}

__global__ __launch_bounds__(128)
#if HAS_TCGEN05
__cluster_dims__(1, 1, 1)
#endif
void braid_attn_tc()
{
    const int bh = blockIdx.y;
    const int b  = bh >> 4;
    const int h  = bh & 15;
    const int kh = h >> 1;
    const int t0 = (int)(gridDim.x - 1 - blockIdx.x) * 128;
    const int tl = threadIdx.x;
    const int t  = t0 + tl;
    const float sq = g_sq[(size_t)bh * TDIM + t];
    const float* skb  = g_sk + ((size_t)b * NKV + kh) * TDIM;
    const float* vsrc = g_qkv + (size_t)b * TDIM * QKV_COLS + 1536 + kh * HDIM;

#if HAS_TCGEN05
    extern __shared__ char smem[];
    const uint32_t sbase = smem_u32(smem);
    const int wid  = tl >> 5;

    if (wid == 0) { TC_ALLOC(sbase + ATT_TMPTR, 64); }
    if (tl == 0)  { MBAR_INIT(sbase + ATT_MBAR, 1); }
    __syncthreads();
    uint32_t tmem;
    asm volatile("ld.shared.b32 %0, [%1];" : "=r"(tmem) : "r"(sbase + ATT_TMPTR));

    const float E = __expf(-fminf(fmaxf(sq, -80.f), 80.f));
    float* eskp = (float*)(smem + ATT_ESK);

    uint32_t ph = 0;
    const int ntiles = t0 / 128 + 1;
    for (int it = 0; it < ntiles; ++it) {
        const int s0 = it * 128;
        if (it > 0) { mbar_wait(sbase + ATT_MBAR, ph); ph ^= 1; }   // SMEM free

        {
            float skv = skb[s0 + tl];
            eskp[tl] = __expf(-fminf(fmaxf(skv, -80.f), 80.f));
        }

        // V^T tile: [64 d rows x 128 s] bf16 hi/lo, blocked-atom + SW128
        #pragma unroll 4
        for (int i = 0; i < 32; i++) {
            const int idx = i * 128 + tl;
            const int d  = idx & 63;
            const int s  = (idx >> 6) * 2;
            const float v0 = vsrc[(size_t)(s0 + s)     * QKV_COLS + d];
            const float v1 = vsrc[(size_t)(s0 + s + 1) * QKV_COLS + d];
            __nv_bfloat162 h2 = __floats2bfloat162_rn(v0, v1);
            float l0 = v0 - __bfloat162float(__low2bfloat16(h2));
            float l1 = v1 - __bfloat162float(__high2bfloat16(h2));
            __nv_bfloat162 l2 = __floats2bfloat162_rn(l0, l1);
            const uint32_t off = SW128(b_off(d, s));
            *(__nv_bfloat162*)(smem + ATT_VH + off) = h2;
            *(__nv_bfloat162*)(smem + ATT_VL + off) = l2;
        }
        __syncthreads();   // esk table complete before P loop

        // P row: p = 1/(1 + E*esk[s]), causal-masked
        const int lim = (s0 == t0) ? tl : 127;
        #pragma unroll 4
        for (int j = 0; j < 64; j++) {
            const int s = 2 * j;
            const float2 e2 = ((const float2*)eskp)[j];
            float p0 = (s     <= lim) ? __fdividef(1.f, fmaf(E, e2.x, 1.f)) : 0.f;
            float p1 = (s + 1 <= lim) ? __fdividef(1.f, fmaf(E, e2.y, 1.f)) : 0.f;
            __nv_bfloat162 h2 = __floats2bfloat162_rn(p0, p1);
            float l0 = p0 - __bfloat162float(__low2bfloat16(h2));
            float l1 = p1 - __bfloat162float(__high2bfloat16(h2));
            __nv_bfloat162 l2 = __floats2bfloat162_rn(l0, l1);
            const uint32_t off = SW128(a_off(tl, s));
            *(__nv_bfloat162*)(smem + ATT_PH + off) = h2;
            *(__nv_bfloat162*)(smem + ATT_PL + off) = l2;
        }
        TC_FENCE_BEFORE();
        __syncthreads();

        if (wid == 0) {
            TC_FENCE_AFTER();
            if (elect_one()) {
                const uint64_t pa_h = mk_desc(sbase + ATT_PH);
                const uint64_t pa_l = mk_desc(sbase + ATT_PL);
                const uint64_t vb_h = mk_desc(sbase + ATT_VH);
                const uint64_t vb_l = mk_desc(sbase + ATT_VL);
                #pragma unroll
                for (int term = 0; term < 3; term++) {
                    const uint64_t ad = (term == 2) ? pa_l : pa_h;
                    const uint64_t bd = (term == 1) ? vb_l : vb_h;
                    #pragma unroll
                    for (int ks = 0; ks < 8; ks++) {
                        const uint64_t ao = (ks < 4) ? (uint64_t)(ks * 2) : (uint64_t)(1024 + (ks - 4) * 2);
                        const uint64_t bo = (ks < 4) ? (uint64_t)(ks * 2) : (uint64_t)(512  + (ks - 4) * 2);
                        tc_mma_f16_ss(tmem, ad + ao, bd + bo, ATT_IDESC,
                                      (it == 0 && term == 0 && ks == 0) ? 0u : 1u);
                    }
                }
                TC_COMMIT(sbase + ATT_MBAR);
            }
        }
    }

    mbar_wait(sbase + ATT_MBAR, ph);
    TC_FENCE_AFTER();

    uint32_t r[64];
    ldtm_x32(r,      tmem);
    ldtm_x32(r + 32, tmem + 32);
    TC_WAIT_LD();
    TC_FENCE_BEFORE();

    const float inv = 1.0f / (45.25483399593904f + 1e-6f);
    __nv_bfloat16* yh = g_yhi + (size_t)(b * TDIM + t) * CDIM + h * HDIM;
    __nv_bfloat16* yl = g_ylo + (size_t)(b * TDIM + t) * CDIM + h * HDIM;
    #pragma unroll
    for (int i = 0; i < 64; i += 2) {
        float v0 = __uint_as_float(r[i])   * inv;
        float v1 = __uint_as_float(r[i+1]) * inv;
        __nv_bfloat162 h2 = __floats2bfloat162_rn(v0, v1);
        float l0 = v0 - __bfloat162float(__low2bfloat16(h2));
        float l1 = v1 - __bfloat162float(__high2bfloat16(h2));
        *(__nv_bfloat162*)(yh + i) = h2;
        *(__nv_bfloat162*)(yl + i) = __floats2bfloat162_rn(l0, l1);
    }
    __syncthreads();
    if (wid == 0) { TC_DEALLOC(tmem, 64); }
#else
    // -------- FFMA fallback (compile-only on non-103a pass) ------------------
    float acc[64];
    #pragma unroll
    for (int i = 0; i < 64; i++) acc[i] = 0.f;
    for (int s = 0; s <= t; s++) {
        float p = __fdividef(1.0f, 1.0f + __expf(-(sq + skb[s])));
        const float* vr = vsrc + (size_t)s * QKV_COLS;
        #pragma unroll
        for (int i = 0; i < 64; i++) acc[i] = fmaf(p, vr[i], acc[i]);
    }
    const float inv = 1.0f / (45.25483399593904f + 1e-6f);
    __nv_bfloat16* yh = g_yhi + (size_t)(b * TDIM + t) * CDIM + h * HDIM;
    __nv_bfloat16* yl = g_ylo + (size_t)(b * TDIM + t) * CDIM + h * HDIM;
    #pragma unroll
    for (int i = 0; i < 64; i += 2) {
        float v0 = acc[i] * inv, v1 = acc[i+1] * inv;
        __nv_bfloat162 h2 = __floats2bfloat162_rn(v0, v1);
        float l0 = v0 - __bfloat162float(__low2bfloat16(h2));
        float l1 = v1 - __bfloat162float(__high2bfloat16(h2));
        *(__nv_bfloat162*)(yh + i) = h2;
        *(__nv_bfloat162*)(yl + i) = __floats2bfloat162_rn(l0, l1);
    }
#endif
}

// -------------------- host: tensor-map construction --------------------------
typedef CUresult (*PFN_tmEncode)(
    CUtensorMap*, CUtensorMapDataType, cuuint32_t, void*,
    const cuuint64_t*, const cuuint64_t*, const cuuint32_t*, const cuuint32_t*,
    CUtensorMapInterleave, CUtensorMapSwizzle, CUtensorMapL2promotion,
    CUtensorMapFloatOOBfill);

static void make_map2d(PFN_tmEncode enc, CUtensorMap* m, void* ptr,
                       unsigned long long d0, unsigned long long d1)
{
    cuuint64_t dims[2]    = {d0, d1};
    cuuint64_t strides[1] = {d0 * 2};                 // bytes per row (bf16)
    cuuint32_t box[2]     = {64, 128};                // 128B rows: SW128 legal
    cuuint32_t es[2]      = {1, 1};
    enc(m, CU_TENSOR_MAP_DATA_TYPE_BFLOAT16, 2, ptr, dims, strides, box, es,
        CU_TENSOR_MAP_INTERLEAVE_NONE, CU_TENSOR_MAP_SWIZZLE_128B,
        CU_TENSOR_MAP_L2_PROMOTION_L2_128B, CU_TENSOR_MAP_FLOAT_OOB_FILL_NONE);
}

// -----------------------------------------------------------------------------
extern "C" void kernel_launch(void* const* d_in, const int* in_sizes, int n_in,
                              void* d_out, int out_size)
{
    const float* x     = (const float*)d_in[0];
    const float* cosb  = (const float*)d_in[1];
    const float* sinb  = (const float*)d_in[2];
    const float* Wq    = (const float*)d_in[3];
    const float* Wk    = (const float*)d_in[4];
    const float* Wv    = (const float*)d_in[5];
    const float* Wproj = (const float*)d_in[6];
    const float* wb    = (const float*)d_in[7];
    float* out = (float*)d_out;

    float *qkv, *sq, *sk;
    cudaGetSymbolAddress((void**)&qkv, g_qkv);
    cudaGetSymbolAddress((void**)&sq,  g_sq);
    cudaGetSymbolAddress((void**)&sk,  g_sk);

    __nv_bfloat16 *xhi, *xlo, *wqkvh, *wqkvl, *wph, *wpl, *yhi, *ylo;
    cudaGetSymbolAddress((void**)&xhi,   g_xhi);    cudaGetSymbolAddress((void**)&xlo,   g_xlo);
    cudaGetSymbolAddress((void**)&wqkvh, g_wqkvh);  cudaGetSymbolAddress((void**)&wqkvl, g_wqkvl);
    cudaGetSymbolAddress((void**)&wph,   g_wph);    cudaGetSymbolAddress((void**)&wpl,   g_wpl);
    cudaGetSymbolAddress((void**)&yhi,   g_yhi);    cudaGetSymbolAddress((void**)&ylo,   g_ylo);

    // driver entry point for tensor-map encode (no -lcuda needed)
    PFN_tmEncode enc = nullptr;
    {
        cudaDriverEntryPointQueryResult qr;
        cudaGetDriverEntryPoint("cuTensorMapEncodeTiled", (void**)&enc,
                                cudaEnableDefault, &qr);
    }
    CUtensorMap mXhi, mXlo, mWqkvh, mWqkvl, mWph, mWpl, mYhi, mYlo;
    make_map2d(enc, &mXhi,   xhi,   CDIM, MROWS);
    make_map2d(enc, &mXlo,   xlo,   CDIM, MROWS);
    make_map2d(enc, &mWqkvh, wqkvh, CDIM, QKV_COLS);
    make_map2d(enc, &mWqkvl, wqkvl, CDIM, QKV_COLS);
    make_map2d(enc, &mWph,   wph,   CDIM, CDIM);
    make_map2d(enc, &mWpl,   wpl,   CDIM, CDIM);
    make_map2d(enc, &mYhi,   yhi,   CDIM, MROWS);
    make_map2d(enc, &mYlo,   ylo,   CDIM, MROWS);

    cudaFuncSetAttribute(gemm3_bf16,    cudaFuncAttributeMaxDynamicSharedMemorySize, SMEM_GEMM);
    cudaFuncSetAttribute(braid_attn_tc, cudaFuncAttributeMaxDynamicSharedMemorySize, SMEM_ATTN);

    // hi/lo bf16 splits (Wq|Wk|Wv go into one fused weight buffer)
    {
        int n4;
        n4 = MROWS*CDIM/4;      split_bf16<<<(n4+255)/256, 256>>>(x,     xhi, xlo, n4);
        n4 = CDIM*CDIM/4;       split_bf16<<<(n4+255)/256, 256>>>(Wq,    wqkvh,             wqkvl,             n4);
        n4 = (NKV*HDIM)*CDIM/4; split_bf16<<<(n4+255)/256, 256>>>(Wk,    wqkvh + 1024*CDIM, wqkvl + 1024*CDIM, n4);
        n4 = (NKV*HDIM)*CDIM/4; split_bf16<<<(n4+255)/256, 256>>>(Wv,    wqkvh + 1536*CDIM, wqkvl + 1536*CDIM, n4);
        n4 = CDIM*CDIM/4;       split_bf16<<<(n4+255)/256, 256>>>(Wproj, wph, wpl, n4);
    }

    // fused QKV projection: [4096 x 2048] = x @ [Wq|Wk|Wv]^T on tcgen05 + TMA
    gemm3_bf16<<<dim3(QKV_COLS/128, MROWS/128), 256, SMEM_GEMM>>>(
        mXhi, mXlo, mWqkvh, mWqkvl,
        xhi, xlo, wqkvh, wqkvl, qkv, MROWS, QKV_COLS, CDIM);

    // RoPE + RMSnorm + braid scalar (q cols 0..1023, k cols 1024..1535)
    rope_braid<<<(BDIM*TDIM*NH  + 7) / 8, 256>>>(qkv, sq, cosb, sinb, wb, NH,  0);
    rope_braid<<<(BDIM*TDIM*NKV + 7) / 8, 256>>>(qkv, sk, cosb, sinb, wb, NKV, 1024);

    // tensor-core sigmoid-braid causal attention -> y (bf16 hi/lo)
    braid_attn_tc<<<dim3(TDIM/128, BDIM*NH), 128, SMEM_ATTN>>>();

    // output projection
    gemm3_bf16<<<dim3(CDIM/128, MROWS/128), 256, SMEM_GEMM>>>(
        mYhi, mYlo, mWph, mWpl,
        yhi, ylo, wph, wpl, out, MROWS, CDIM, CDIM);
}